// round 7
// baseline (speedup 1.0000x reference)
#include <cuda_runtime.h>
#include <cuda_bf16.h>
#include <math.h>
#include <stdint.h>

#define N    8192
#define D    256
#define INV_T (1.0f / 0.7f)
#define QSCALE 254.0f
#define SCSQ  (1.0f / (QSCALE * QSCALE))
#define EXQ   (1.44269504088896f * INV_T * SCSQ)   // log2(e)/T * SC^2

#define TM 128
#define TN 128
#define GI (N / TM)                  // 64
#define NTILES (GI * (GI + 1) / 2)   // 2080

// ---------------- device scratch ----------------
__device__ __align__(128) int8_t g_Pq[N * D];   // quantized rows, 256 B/row
__device__ float g_A[N];
__device__ float g_B[N];
__device__ int   g_selfint[N];
__device__ int   g_cls[N];

// ---------------- helpers ----------------
__device__ __forceinline__ uint32_t smem_u32(const void* p) {
    uint32_t a;
    asm("{ .reg .u64 t; cvta.to.shared.u64 t, %1; cvt.u32.u64 %0, t; }"
        : "=r"(a) : "l"(p));
    return a;
}
#define SW128(off) ((off) ^ (((off) >> 3) & 0x70))

__device__ __forceinline__ void cp16(uint32_t dst, const void* src) {
    asm volatile("cp.async.cg.shared.global [%0], [%1], 16;" :: "r"(dst), "l"(src));
}
__device__ __forceinline__ void cp_commit() {
    asm volatile("cp.async.commit_group;" ::: "memory");
}
__device__ __forceinline__ void ldsm4(uint32_t& r0, uint32_t& r1,
                                      uint32_t& r2, uint32_t& r3, uint32_t addr) {
    asm volatile("ldmatrix.sync.aligned.m8n8.x4.shared.b16 {%0,%1,%2,%3}, [%4];"
                 : "=r"(r0), "=r"(r1), "=r"(r2), "=r"(r3) : "r"(addr));
}
__device__ __forceinline__ void mma16832(int* d, const uint32_t* a,
                                         const uint32_t* b) {
    asm volatile("mma.sync.aligned.m16n8k32.row.col.s32.s8.s8.s32 "
                 "{%0,%1,%2,%3}, {%4,%5,%6,%7}, {%8,%9}, {%0,%1,%2,%3};"
                 : "+r"(d[0]), "+r"(d[1]), "+r"(d[2]), "+r"(d[3])
                 : "r"(a[0]), "r"(a[1]), "r"(a[2]), "r"(a[3]),
                   "r"(b[0]), "r"(b[1]));
}
__device__ __forceinline__ float ex2(float x) {
    float r;
    asm("ex2.approx.f32 %0, %1;" : "=f"(r) : "f"(x));
    return r;
}

// ---------------- SMEM layout: 2 int8 chunks (k 0..127 / 128..255) ----------
#define ACH(c) ((c) * 16384)             // 128 rows x 128 B, SW128
#define BCH(c) (32768 + (c) * 16384)
#define CLSI_OFF  65536
#define CLSJ_OFF  66048
#define SACCI_OFF 66560
#define SBCCI_OFF 67072
#define SACCJ_OFF 67584
#define SBCCJ_OFF 68096
#define SMEM_BYTES 68608

// ---------------------------------------------------------------------------
// k_norm: dtype detect + zero A/B + normalize + int8 quantize + selfdot + cls
// ---------------------------------------------------------------------------
__global__ void k_norm(const float* __restrict__ P, const void* __restrict__ yv) {
    __shared__ int s_is64;
    const int tid  = threadIdx.x;
    const int w    = tid >> 5;
    const int lane = tid & 31;
    const int row  = blockIdx.x * 8 + w;

    if (w == 0) {   // int64 y<10 => all odd 32-bit words zero
        int v = ((const int*)yv)[2 * lane + 1];
        unsigned any = __ballot_sync(0xffffffffu, v != 0);
        if (lane == 0) s_is64 = (any == 0) ? 1 : 0;
    }
    if (blockIdx.x < 32) {
        int idx = blockIdx.x * 256 + tid;
        g_A[idx] = 0.0f; g_B[idx] = 0.0f;
    }
    __syncthreads();
    const int is64 = s_is64;

    const float4* p4 = (const float4*)(P + (size_t)row * D);
    float4 v0 = p4[lane];
    float4 v1 = p4[lane + 32];

    float ss = v0.x*v0.x + v0.y*v0.y + v0.z*v0.z + v0.w*v0.w
             + v1.x*v1.x + v1.y*v1.y + v1.z*v1.z + v1.w*v1.w;
    #pragma unroll
    for (int o = 16; o; o >>= 1) ss += __shfl_xor_sync(0xffffffffu, ss, o);
    const float rq = rsqrtf(ss) * QSCALE;

    float f[8] = {v0.x, v0.y, v0.z, v0.w, v1.x, v1.y, v1.z, v1.w};
    int   q[8];
    int   sq = 0;
    #pragma unroll
    for (int e = 0; e < 8; e++) {
        int v = __float2int_rn(f[e] * rq);
        v = max(-127, min(127, v));
        q[e] = v;
        sq += v * v;
    }
    #pragma unroll
    for (int o = 16; o; o >>= 1) sq += __shfl_xor_sync(0xffffffffu, sq, o);

    uint32_t w0 = (uint32_t)(q[0] & 255) | ((uint32_t)(q[1] & 255) << 8)
                | ((uint32_t)(q[2] & 255) << 16) | ((uint32_t)q[3] << 24);
    uint32_t w1 = (uint32_t)(q[4] & 255) | ((uint32_t)(q[5] & 255) << 8)
                | ((uint32_t)(q[6] & 255) << 16) | ((uint32_t)q[7] << 24);
    *(uint32_t*)(g_Pq + (size_t)row * D + lane * 4)       = w0;
    *(uint32_t*)(g_Pq + (size_t)row * D + 128 + lane * 4) = w1;

    if (lane == 0) {
        int c = is64 ? (int)((const long long*)yv)[row] : ((const int*)yv)[row];
        g_cls[row]     = c;
        g_selfint[row] = sq;
    }
}

// ---------------------------------------------------------------------------
__device__ __forceinline__ void load_frags(uint32_t aB, uint32_t bB, int ks,
                                           int m0, int n0, int lrow, int lkoff,
                                           uint32_t afr[4][4], uint32_t bfr[4][2]) {
    #pragma unroll
    for (int nf2 = 0; nf2 < 2; nf2++) {
        uint32_t r0, r1, r2, r3;
        uint32_t off = (uint32_t)((n0 + nf2 * 16 + lrow) * 128 + lkoff + ks * 32);
        ldsm4(r0, r1, r2, r3, bB + SW128(off));
        bfr[nf2 * 2 + 0][0] = r0; bfr[nf2 * 2 + 0][1] = r2;
        bfr[nf2 * 2 + 1][0] = r1; bfr[nf2 * 2 + 1][1] = r3;
    }
    #pragma unroll
    for (int mf = 0; mf < 4; mf++) {
        uint32_t off = (uint32_t)((m0 + mf * 16 + lrow) * 128 + lkoff + ks * 32);
        ldsm4(afr[mf][0], afr[mf][1], afr[mf][2], afr[mf][3], aB + SW128(off));
    }
}

template<int CK>
__device__ __forceinline__ void do_chunk(uint32_t sbase, int m0, int n0,
                                         int lrow, int lkoff,
                                         uint32_t afr[2][4][4], uint32_t bfr[2][4][2],
                                         int acc[4][4][4]) {
    asm volatile("cp.async.wait_group %0;" :: "n"(1 - CK) : "memory");
    __syncthreads();
    const uint32_t aB = sbase + ACH(CK);
    const uint32_t bB = sbase + BCH(CK);
    load_frags(aB, bB, 0, m0, n0, lrow, lkoff, afr[0], bfr[0]);
    #pragma unroll
    for (int ks = 0; ks < 4; ks++) {
        const int cur = ks & 1;
        if (ks < 3)
            load_frags(aB, bB, ks + 1, m0, n0, lrow, lkoff, afr[cur ^ 1], bfr[cur ^ 1]);
        #pragma unroll
        for (int mf = 0; mf < 4; mf++)
            #pragma unroll
            for (int nf = 0; nf < 4; nf++)
                mma16832(acc[mf][nf], afr[cur][mf], bfr[cur][nf]);
    }
}

// ---------------------------------------------------------------------------
// k_main: upper-triangle 128x128 tiles, int8 MMA, fused exp epilogue
// ---------------------------------------------------------------------------
__global__ void __launch_bounds__(256, 1) k_main() {
    extern __shared__ __align__(128) unsigned char smem[];
    const uint32_t sbase = smem_u32(smem);
    const int tid  = threadIdx.x;
    const int wid  = tid >> 5;
    const int lane = tid & 31;

    int biBlk = 0, rem = blockIdx.x;
    #pragma unroll 1
    while (rem >= GI - biBlk) { rem -= GI - biBlk; biBlk++; }
    const int bjBlk = biBlk + rem;
    const bool offdiag = (biBlk != bjBlk);

    const int iBase = biBlk * TM;
    const int jBase = bjBlk * TN;

    int*   clsI  = (int*)(smem + CLSI_OFF);
    int*   clsJ  = (int*)(smem + CLSJ_OFF);
    float* sAccI = (float*)(smem + SACCI_OFF);
    float* sBccI = (float*)(smem + SBCCI_OFF);
    float* sAccJ = (float*)(smem + SACCJ_OFF);
    float* sBccJ = (float*)(smem + SBCCJ_OFF);

    // 2 chunks, one cp.async group each (4 cp16/thread per matrix per chunk... 4 total)
    #pragma unroll
    for (int ck = 0; ck < 2; ck++) {
        #pragma unroll
        for (int q = 0; q < 4; q++) {
            int s  = tid + q * 256;      // 0..1023 : 128 rows x 8 segs
            int r  = s >> 3;
            int sg = s & 7;
            uint32_t soff = SW128((uint32_t)(r * 128 + sg * 16));
            cp16(sbase + ACH(ck) + soff,
                 g_Pq + (size_t)(iBase + r) * D + ck * 128 + sg * 16);
            cp16(sbase + BCH(ck) + soff,
                 g_Pq + (size_t)(jBase + r) * D + ck * 128 + sg * 16);
        }
        cp_commit();
    }

    if (tid < 128) {
        clsI[tid] = g_cls[iBase + tid];
        sAccI[tid] = 0.0f; sBccI[tid] = 0.0f;
    } else {
        clsJ[tid - 128] = g_cls[jBase + tid - 128];
        sAccJ[tid - 128] = 0.0f; sBccJ[tid - 128] = 0.0f;
    }

    const int m0 = (wid >> 2) * 64;
    const int n0 = (wid & 3) * 32;
    const int lrow  = lane & 15;
    const int lkoff = (lane >> 4) * 16;

    int acc[4][4][4];
    #pragma unroll
    for (int mf = 0; mf < 4; mf++)
        #pragma unroll
        for (int nf = 0; nf < 4; nf++)
            #pragma unroll
            for (int e = 0; e < 4; e++) acc[mf][nf][e] = 0;

    uint32_t afr[2][4][4], bfr[2][4][2];
    do_chunk<0>(sbase, m0, n0, lrow, lkoff, afr, bfr, acc);
    do_chunk<1>(sbase, m0, n0, lrow, lkoff, afr, bfr, acc);

    // ---- epilogue: diag self-term handled in k_loss ----
    const int gl   = lane >> 2;
    const int quad = lane & 3;

    int cjr[8];
    #pragma unroll
    for (int q = 0; q < 8; q++) cjr[q] = clsJ[n0 + (q >> 1) * 8 + quad * 2 + (q & 1)];

    float aCol[8], bCol[8];
    #pragma unroll
    for (int q = 0; q < 8; q++) { aCol[q] = 0.0f; bCol[q] = 0.0f; }

    #pragma unroll
    for (int rr = 0; rr < 2; rr++) {
        #pragma unroll
        for (int mf = 0; mf < 4; mf++) {
            const int rl = m0 + mf * 16 + gl + rr * 8;
            const int ci = clsI[rl];
            float aRow = 0.0f, bRow = 0.0f;
            #pragma unroll
            for (int q = 0; q < 8; q++) {
                const float s = (float)acc[mf][q >> 1][rr * 2 + (q & 1)];
                const bool same = (ci == cjr[q]);
                const float v = ex2(s * (same ? -EXQ : EXQ));
                const float va = same ? 0.0f : v;
                const float vb = v - va;
                aRow += va; bRow += vb;
                aCol[q] += va; bCol[q] += vb;
            }
            aRow += __shfl_xor_sync(0xffffffffu, aRow, 1);
            aRow += __shfl_xor_sync(0xffffffffu, aRow, 2);
            bRow += __shfl_xor_sync(0xffffffffu, bRow, 1);
            bRow += __shfl_xor_sync(0xffffffffu, bRow, 2);
            if (quad == 0) {
                atomicAdd(&sAccI[rl], aRow);
                atomicAdd(&sBccI[rl], bRow);
            }
        }
    }

    if (offdiag) {
        #pragma unroll
        for (int q = 0; q < 8; q++) {
            float a = aCol[q], b = bCol[q];
            #pragma unroll
            for (int o = 4; o <= 16; o <<= 1) {
                a += __shfl_xor_sync(0xffffffffu, a, o);
                b += __shfl_xor_sync(0xffffffffu, b, o);
            }
            if (lane < 4) {
                const int cl = n0 + (q >> 1) * 8 + quad * 2 + (q & 1);
                atomicAdd(&sAccJ[cl], a);
                atomicAdd(&sBccJ[cl], b);
            }
        }
    }

    __syncthreads();
    if (tid < 128) {
        atomicAdd(&g_A[iBase + tid], sAccI[tid]);
        atomicAdd(&g_B[iBase + tid], sBccI[tid]);
        if (offdiag) {
            atomicAdd(&g_A[jBase + tid], sAccJ[tid]);
            atomicAdd(&g_B[jBase + tid], sBccJ[tid]);
        }
    }
}

// ---------------------------------------------------------------------------
// k_loss: histogram, subtract exact self term, empty-set semantics, mean
// ---------------------------------------------------------------------------
__global__ void k_loss(float* __restrict__ out) {
    __shared__ float red[256];
    __shared__ int hist[16];
    const int tid = threadIdx.x;
    if (tid < 16) hist[tid] = 0;
    __syncthreads();
    for (int r = tid; r < N; r += 256) atomicAdd(&hist[g_cls[r] & 15], 1);
    __syncthreads();

    const float MF = __expf(0.5f * INV_T);
    float sum = 0.0f;
    for (int r = tid; r < N; r += 256) {
        int   c   = g_cls[r] & 15;
        int   cnt = hist[c];
        float Bv  = g_B[r] - __expf(-(float)g_selfint[r] * SCSQ * INV_T);
        float Av  = (N - cnt > 0) ? g_A[r] : 1.0f;
        Bv        = (cnt - 1 > 0) ? Bv : 1.0f;
        sum += log1pf(MF * Av * Bv);
    }
    red[tid] = sum;
    __syncthreads();
    #pragma unroll
    for (int s = 128; s; s >>= 1) {
        if (tid < s) red[tid] += red[tid + s];
        __syncthreads();
    }
    if (tid == 0) out[0] = red[0] / (float)N;
}

// ---------------------------------------------------------------------------
extern "C" void kernel_launch(void* const* d_in, const int* in_sizes, int n_in,
                              void* d_out, int out_size) {
    const float* P = (const float*)d_in[0];
    const void*  y = d_in[1];
    float*     out = (float*)d_out;

    cudaFuncSetAttribute(k_main, cudaFuncAttributeMaxDynamicSharedMemorySize,
                         SMEM_BYTES);

    k_norm<<<N / 8, 256>>>(P, y);
    k_main<<<NTILES, 256, SMEM_BYTES>>>();
    k_loss<<<1, 256>>>(out);
}

// round 8
// speedup vs baseline: 1.4027x; 1.4027x over previous
#include <cuda_runtime.h>
#include <cuda_bf16.h>
#include <math.h>
#include <stdint.h>

#define N    8192
#define D    256
#define INV_T (1.0f / 0.7f)
#define EX2SC (1.44269504088896f * INV_T)   // log2(e)/T

#define TM 128
#define TN 128
#define GI (N / TM)                  // 64
#define NTILES (GI * (GI + 1) / 2)   // 2080

// ---------------- device scratch ----------------
__device__ __nv_bfloat16 g_Pb[N * D];
__device__ float g_A[N];
__device__ float g_B[N];
__device__ float g_selfsim[N];
__device__ int   g_cls[N];
__device__ int   g_done;             // last-block counter (self-resetting)

// ---------------- helpers ----------------
__device__ __forceinline__ uint32_t smem_u32(const void* p) {
    uint32_t a;
    asm("{ .reg .u64 t; cvta.to.shared.u64 t, %1; cvt.u32.u64 %0, t; }"
        : "=r"(a) : "l"(p));
    return a;
}
#define SW128(off) ((off) ^ (((off) >> 3) & 0x70))

__device__ __forceinline__ void cp16(uint32_t dst, const void* src) {
    asm volatile("cp.async.cg.shared.global [%0], [%1], 16;" :: "r"(dst), "l"(src));
}
__device__ __forceinline__ void cp_commit() {
    asm volatile("cp.async.commit_group;" ::: "memory");
}
__device__ __forceinline__ void ldsm4(uint32_t& r0, uint32_t& r1,
                                      uint32_t& r2, uint32_t& r3, uint32_t addr) {
    asm volatile("ldmatrix.sync.aligned.m8n8.x4.shared.b16 {%0,%1,%2,%3}, [%4];"
                 : "=r"(r0), "=r"(r1), "=r"(r2), "=r"(r3) : "r"(addr));
}
__device__ __forceinline__ void mma16816(float* d, const uint32_t* a,
                                         const uint32_t* b) {
    asm volatile("mma.sync.aligned.m16n8k16.row.col.f32.bf16.bf16.f32 "
                 "{%0,%1,%2,%3}, {%4,%5,%6,%7}, {%8,%9}, {%0,%1,%2,%3};"
                 : "+f"(d[0]), "+f"(d[1]), "+f"(d[2]), "+f"(d[3])
                 : "r"(a[0]), "r"(a[1]), "r"(a[2]), "r"(a[3]),
                   "r"(b[0]), "r"(b[1]));
}
__device__ __forceinline__ float ex2(float x) {
    float r;
    asm("ex2.approx.f32 %0, %1;" : "=f"(r) : "f"(x));
    return r;
}

// ---------------- SMEM layout: all 4 bf16 chunks resident ----------------
#define ACH(c) ((c) * 16384)             // A chunk c: 128 rows x 128 B (SW128)
#define BCH(c) (65536 + (c) * 16384)
#define CLSI_OFF  131072
#define CLSJ_OFF  131584
#define SACCI_OFF 132096
#define SBCCI_OFF 132608
#define SACCJ_OFF 133120
#define SBCCJ_OFF 133632
#define SMEM_BYTES 134144

// ---------------------------------------------------------------------------
// k_norm: dtype detect + zero A/B + normalize->bf16 + selfsim + class
// ---------------------------------------------------------------------------
__global__ void k_norm(const float* __restrict__ P, const void* __restrict__ yv) {
    __shared__ int s_is64;
    const int tid  = threadIdx.x;
    const int w    = tid >> 5;
    const int lane = tid & 31;
    const int row  = blockIdx.x * 8 + w;

    if (w == 0) {   // detect: int64 y<10 => all odd 32-bit words zero
        int v = ((const int*)yv)[2 * lane + 1];
        unsigned any = __ballot_sync(0xffffffffu, v != 0);
        if (lane == 0) s_is64 = (any == 0) ? 1 : 0;
    }
    if (blockIdx.x < 32) {              // zero accumulators
        int idx = blockIdx.x * 256 + tid;
        g_A[idx] = 0.0f; g_B[idx] = 0.0f;
    }
    __syncthreads();
    const int is64 = s_is64;

    const float4* p4 = (const float4*)(P + (size_t)row * D);
    float4 v0 = p4[lane];
    float4 v1 = p4[lane + 32];

    float ss = v0.x*v0.x + v0.y*v0.y + v0.z*v0.z + v0.w*v0.w
             + v1.x*v1.x + v1.y*v1.y + v1.z*v1.z + v1.w*v1.w;
    #pragma unroll
    for (int o = 16; o; o >>= 1) ss += __shfl_xor_sync(0xffffffffu, ss, o);
    float rn = rsqrtf(ss);

    __nv_bfloat16 h[8];
    h[0] = __float2bfloat16(v0.x * rn); h[1] = __float2bfloat16(v0.y * rn);
    h[2] = __float2bfloat16(v0.z * rn); h[3] = __float2bfloat16(v0.w * rn);
    h[4] = __float2bfloat16(v1.x * rn); h[5] = __float2bfloat16(v1.y * rn);
    h[6] = __float2bfloat16(v1.z * rn); h[7] = __float2bfloat16(v1.w * rn);

    float sb = 0.0f;
    #pragma unroll
    for (int q = 0; q < 8; q++) { float f = __bfloat162float(h[q]); sb += f * f; }
    #pragma unroll
    for (int o = 16; o; o >>= 1) sb += __shfl_xor_sync(0xffffffffu, sb, o);

    *(uint2*)(g_Pb + (size_t)row * D + lane * 4)       = *(uint2*)&h[0];
    *(uint2*)(g_Pb + (size_t)row * D + 128 + lane * 4) = *(uint2*)&h[4];

    if (lane == 0) {
        int c = is64 ? (int)((const long long*)yv)[row] : ((const int*)yv)[row];
        g_cls[row]     = c;
        g_selfsim[row] = sb;
    }
}

// ---------------------------------------------------------------------------
__device__ __forceinline__ void load_frags(uint32_t aB, uint32_t bB, int ks,
                                           int m0, int n0, int lrow, int lkoff,
                                           uint32_t afr[4][4], uint32_t bfr[4][2]) {
    #pragma unroll
    for (int nf2 = 0; nf2 < 2; nf2++) {
        uint32_t r0, r1, r2, r3;
        uint32_t off = (uint32_t)((n0 + nf2 * 16 + lrow) * 128 + lkoff + ks * 32);
        ldsm4(r0, r1, r2, r3, bB + SW128(off));
        bfr[nf2 * 2 + 0][0] = r0; bfr[nf2 * 2 + 0][1] = r2;
        bfr[nf2 * 2 + 1][0] = r1; bfr[nf2 * 2 + 1][1] = r3;
    }
    #pragma unroll
    for (int mf = 0; mf < 4; mf++) {
        uint32_t off = (uint32_t)((m0 + mf * 16 + lrow) * 128 + lkoff + ks * 32);
        ldsm4(afr[mf][0], afr[mf][1], afr[mf][2], afr[mf][3], aB + SW128(off));
    }
}

template<int CK>
__device__ __forceinline__ void do_chunk(uint32_t sbase, int m0, int n0,
                                         int lrow, int lkoff,
                                         uint32_t afr[2][4][4], uint32_t bfr[2][4][2],
                                         float acc[4][4][4]) {
    asm volatile("cp.async.wait_group %0;" :: "n"(3 - CK) : "memory");
    __syncthreads();
    const uint32_t aB = sbase + ACH(CK);
    const uint32_t bB = sbase + BCH(CK);
    load_frags(aB, bB, 0, m0, n0, lrow, lkoff, afr[0], bfr[0]);
    #pragma unroll
    for (int ks = 0; ks < 4; ks++) {
        const int cur = ks & 1;
        if (ks < 3)
            load_frags(aB, bB, ks + 1, m0, n0, lrow, lkoff, afr[cur ^ 1], bfr[cur ^ 1]);
        #pragma unroll
        for (int mf = 0; mf < 4; mf++)
            #pragma unroll
            for (int nf = 0; nf < 4; nf++)
                mma16816(acc[mf][nf], afr[cur][mf], bfr[cur][nf]);
    }
}

// ---------------------------------------------------------------------------
// k_main: upper-triangle tiles + fused epilogue + last-block finalize
// ---------------------------------------------------------------------------
__global__ void __launch_bounds__(256, 1) k_main(float* __restrict__ out) {
    extern __shared__ __align__(128) unsigned char smem[];
    const uint32_t sbase = smem_u32(smem);
    const int tid  = threadIdx.x;
    const int wid  = tid >> 5;
    const int lane = tid & 31;

    int biBlk = 0, rem = blockIdx.x;
    #pragma unroll 1
    while (rem >= GI - biBlk) { rem -= GI - biBlk; biBlk++; }
    const int bjBlk = biBlk + rem;
    const bool offdiag = (biBlk != bjBlk);

    const int iBase = biBlk * TM;
    const int jBase = bjBlk * TN;

    int*   clsI  = (int*)(smem + CLSI_OFF);
    int*   clsJ  = (int*)(smem + CLSJ_OFF);
    float* sAccI = (float*)(smem + SACCI_OFF);
    float* sBccI = (float*)(smem + SBCCI_OFF);
    float* sAccJ = (float*)(smem + SACCJ_OFF);
    float* sBccJ = (float*)(smem + SBCCJ_OFF);

    #pragma unroll
    for (int ck = 0; ck < 4; ck++) {
        #pragma unroll
        for (int q = 0; q < 4; q++) {
            int s  = tid + q * 256;
            int r  = s >> 3;
            int sg = s & 7;
            uint32_t soff = SW128((uint32_t)(r * 128 + sg * 16));
            cp16(sbase + ACH(ck) + soff,
                 g_Pb + (size_t)(iBase + r) * D + ck * 64 + sg * 8);
            cp16(sbase + BCH(ck) + soff,
                 g_Pb + (size_t)(jBase + r) * D + ck * 64 + sg * 8);
        }
        cp_commit();
    }

    if (tid < 128) {
        clsI[tid] = g_cls[iBase + tid];
        sAccI[tid] = 0.0f; sBccI[tid] = 0.0f;
    } else {
        clsJ[tid - 128] = g_cls[jBase + tid - 128];
        sAccJ[tid - 128] = 0.0f; sBccJ[tid - 128] = 0.0f;
    }

    const int m0 = (wid >> 2) * 64;
    const int n0 = (wid & 3) * 32;
    const int lrow  = lane & 15;
    const int lkoff = (lane >> 4) * 16;

    float acc[4][4][4];
    #pragma unroll
    for (int mf = 0; mf < 4; mf++)
        #pragma unroll
        for (int nf = 0; nf < 4; nf++)
            #pragma unroll
            for (int e = 0; e < 4; e++) acc[mf][nf][e] = 0.0f;

    uint32_t afr[2][4][4], bfr[2][4][2];
    do_chunk<0>(sbase, m0, n0, lrow, lkoff, afr, bfr, acc);
    do_chunk<1>(sbase, m0, n0, lrow, lkoff, afr, bfr, acc);
    do_chunk<2>(sbase, m0, n0, lrow, lkoff, afr, bfr, acc);
    do_chunk<3>(sbase, m0, n0, lrow, lkoff, afr, bfr, acc);

    // ---- epilogue: masked exp; diag self-term removed in finalize ----
    const int gl   = lane >> 2;
    const int quad = lane & 3;

    int cjr[8];
    #pragma unroll
    for (int q = 0; q < 8; q++) cjr[q] = clsJ[n0 + (q >> 1) * 8 + quad * 2 + (q & 1)];

    float aCol[8], bCol[8];
    #pragma unroll
    for (int q = 0; q < 8; q++) { aCol[q] = 0.0f; bCol[q] = 0.0f; }

    #pragma unroll
    for (int rr = 0; rr < 2; rr++) {
        #pragma unroll
        for (int mf = 0; mf < 4; mf++) {
            const int rl = m0 + mf * 16 + gl + rr * 8;
            const int ci = clsI[rl];
            float aRow = 0.0f, bRow = 0.0f;
            #pragma unroll
            for (int q = 0; q < 8; q++) {
                const float s = acc[mf][q >> 1][rr * 2 + (q & 1)];
                const bool same = (ci == cjr[q]);
                const float v = ex2(s * (same ? -EX2SC : EX2SC));
                const float va = same ? 0.0f : v;
                const float vb = v - va;
                aRow += va; bRow += vb;
                aCol[q] += va; bCol[q] += vb;
            }
            aRow += __shfl_xor_sync(0xffffffffu, aRow, 1);
            aRow += __shfl_xor_sync(0xffffffffu, aRow, 2);
            bRow += __shfl_xor_sync(0xffffffffu, bRow, 1);
            bRow += __shfl_xor_sync(0xffffffffu, bRow, 2);
            if (quad == 0) {
                atomicAdd(&sAccI[rl], aRow);
                atomicAdd(&sBccI[rl], bRow);
            }
        }
    }

    if (offdiag) {
        #pragma unroll
        for (int q = 0; q < 8; q++) {
            float a = aCol[q], b = bCol[q];
            #pragma unroll
            for (int o = 4; o <= 16; o <<= 1) {
                a += __shfl_xor_sync(0xffffffffu, a, o);
                b += __shfl_xor_sync(0xffffffffu, b, o);
            }
            if (lane < 4) {
                const int cl = n0 + (q >> 1) * 8 + quad * 2 + (q & 1);
                atomicAdd(&sAccJ[cl], a);
                atomicAdd(&sBccJ[cl], b);
            }
        }
    }

    __syncthreads();
    if (tid < 128) {
        atomicAdd(&g_A[iBase + tid], sAccI[tid]);
        atomicAdd(&g_B[iBase + tid], sBccI[tid]);
        if (offdiag) {
            atomicAdd(&g_A[jBase + tid], sAccJ[tid]);
            atomicAdd(&g_B[jBase + tid], sBccJ[tid]);
        }
    }

    // ---- last-block finalize (replaces k_loss launch) ----
    __threadfence();
    __shared__ int s_rank;
    __syncthreads();
    if (tid == 0) s_rank = atomicAdd(&g_done, 1);
    __syncthreads();
    if (s_rank == NTILES - 1) {
        __threadfence();
        float* red  = sAccI;                 // reuse smem
        int*   hist = clsI;
        if (tid < 16) hist[tid] = 0;
        __syncthreads();
        for (int r = tid; r < N; r += 256) atomicAdd(&hist[g_cls[r] & 15], 1);
        __syncthreads();

        const float MF = __expf(0.5f * INV_T);
        float sum = 0.0f;
        for (int r = tid; r < N; r += 256) {
            int   c   = g_cls[r] & 15;
            int   cnt = hist[c];
            float Bv  = __ldcg(&g_B[r]) - __expf(-g_selfsim[r] * INV_T);
            float Av  = (N - cnt > 0) ? __ldcg(&g_A[r]) : 1.0f;
            Bv        = (cnt - 1 > 0) ? Bv : 1.0f;
            sum += log1pf(MF * Av * Bv);
        }
        red[tid] = sum;
        __syncthreads();
        #pragma unroll
        for (int s = 128; s; s >>= 1) {
            if (tid < s) red[tid] += red[tid + s];
            __syncthreads();
        }
        if (tid == 0) {
            out[0] = red[0] / (float)N;
            g_done = 0;                      // reset for next graph replay
        }
    }
}

// ---------------------------------------------------------------------------
extern "C" void kernel_launch(void* const* d_in, const int* in_sizes, int n_in,
                              void* d_out, int out_size) {
    const float* P = (const float*)d_in[0];
    const void*  y = d_in[1];
    float*     out = (float*)d_out;

    cudaFuncSetAttribute(k_main, cudaFuncAttributeMaxDynamicSharedMemorySize,
                         SMEM_BYTES);

    k_norm<<<N / 8, 256>>>(P, y);
    k_main<<<NTILES, 256, SMEM_BYTES>>>(out);
}

// round 9
// speedup vs baseline: 1.6145x; 1.1510x over previous
#include <cuda_runtime.h>
#include <cuda_bf16.h>
#include <math.h>
#include <stdint.h>

#define N    8192
#define D    256
#define INV_T (1.0f / 0.7f)
#define EX2SC (1.44269504088896f * INV_T)   // log2(e)/T

#define TM 128
#define TN 128
#define GI (N / TM)                  // 64
#define NTILES (GI * (GI + 1) / 2)   // 2080

// ---------------- device scratch ----------------
__device__ __nv_bfloat16 g_Pb[N * D];
__device__ float g_A[N];
__device__ float g_B[N];
__device__ float g_selfsim[N];
__device__ int   g_cls[N];

// ---------------- helpers ----------------
__device__ __forceinline__ uint32_t smem_u32(const void* p) {
    uint32_t a;
    asm("{ .reg .u64 t; cvta.to.shared.u64 t, %1; cvt.u32.u64 %0, t; }"
        : "=r"(a) : "l"(p));
    return a;
}
#define SW128(off) ((off) ^ (((off) >> 3) & 0x70))

__device__ __forceinline__ void cp16(uint32_t dst, const void* src) {
    asm volatile("cp.async.cg.shared.global [%0], [%1], 16;" :: "r"(dst), "l"(src));
}
__device__ __forceinline__ void cp_commit() {
    asm volatile("cp.async.commit_group;" ::: "memory");
}
__device__ __forceinline__ void ldsm4(uint32_t& r0, uint32_t& r1,
                                      uint32_t& r2, uint32_t& r3, uint32_t addr) {
    asm volatile("ldmatrix.sync.aligned.m8n8.x4.shared.b16 {%0,%1,%2,%3}, [%4];"
                 : "=r"(r0), "=r"(r1), "=r"(r2), "=r"(r3) : "r"(addr));
}
__device__ __forceinline__ void mma16816(float* d, const uint32_t* a,
                                         const uint32_t* b) {
    asm volatile("mma.sync.aligned.m16n8k16.row.col.f32.bf16.bf16.f32 "
                 "{%0,%1,%2,%3}, {%4,%5,%6,%7}, {%8,%9}, {%0,%1,%2,%3};"
                 : "+f"(d[0]), "+f"(d[1]), "+f"(d[2]), "+f"(d[3])
                 : "r"(a[0]), "r"(a[1]), "r"(a[2]), "r"(a[3]),
                   "r"(b[0]), "r"(b[1]));
}
__device__ __forceinline__ float ex2(float x) {
    float r;
    asm("ex2.approx.f32 %0, %1;" : "=f"(r) : "f"(x));
    return r;
}

// ---------------- SMEM layout: all 4 bf16 chunks resident ----------------
#define ACH(c) ((c) * 16384)             // A chunk c: 128 rows x 128 B (SW128)
#define BCH(c) (65536 + (c) * 16384)
#define CLSI_OFF  131072
#define CLSJ_OFF  131584
#define SACCI_OFF 132096
#define SBCCI_OFF 132608
#define SACCJ_OFF 133120
#define SBCCJ_OFF 133632
#define SMEM_BYTES 134144

// ---------------------------------------------------------------------------
// k_norm: dtype detect + zero A/B + normalize->bf16 + selfsim + class
// ---------------------------------------------------------------------------
__global__ void k_norm(const float* __restrict__ P, const void* __restrict__ yv) {
    __shared__ int s_is64;
    const int tid  = threadIdx.x;
    const int w    = tid >> 5;
    const int lane = tid & 31;
    const int row  = blockIdx.x * 8 + w;

    if (w == 0) {   // detect: int64 y<10 => all odd 32-bit words zero
        int v = ((const int*)yv)[2 * lane + 1];
        unsigned any = __ballot_sync(0xffffffffu, v != 0);
        if (lane == 0) s_is64 = (any == 0) ? 1 : 0;
    }
    if (blockIdx.x < 32) {              // zero accumulators
        int idx = blockIdx.x * 256 + tid;
        g_A[idx] = 0.0f; g_B[idx] = 0.0f;
    }
    __syncthreads();
    const int is64 = s_is64;

    const float4* p4 = (const float4*)(P + (size_t)row * D);
    float4 v0 = p4[lane];
    float4 v1 = p4[lane + 32];

    float ss = v0.x*v0.x + v0.y*v0.y + v0.z*v0.z + v0.w*v0.w
             + v1.x*v1.x + v1.y*v1.y + v1.z*v1.z + v1.w*v1.w;
    #pragma unroll
    for (int o = 16; o; o >>= 1) ss += __shfl_xor_sync(0xffffffffu, ss, o);
    float rn = rsqrtf(ss);

    __nv_bfloat16 h[8];
    h[0] = __float2bfloat16(v0.x * rn); h[1] = __float2bfloat16(v0.y * rn);
    h[2] = __float2bfloat16(v0.z * rn); h[3] = __float2bfloat16(v0.w * rn);
    h[4] = __float2bfloat16(v1.x * rn); h[5] = __float2bfloat16(v1.y * rn);
    h[6] = __float2bfloat16(v1.z * rn); h[7] = __float2bfloat16(v1.w * rn);

    float sb = 0.0f;
    #pragma unroll
    for (int q = 0; q < 8; q++) { float f = __bfloat162float(h[q]); sb += f * f; }
    #pragma unroll
    for (int o = 16; o; o >>= 1) sb += __shfl_xor_sync(0xffffffffu, sb, o);

    *(uint2*)(g_Pb + (size_t)row * D + lane * 4)       = *(uint2*)&h[0];
    *(uint2*)(g_Pb + (size_t)row * D + 128 + lane * 4) = *(uint2*)&h[4];

    if (lane == 0) {
        int c = is64 ? (int)((const long long*)yv)[row] : ((const int*)yv)[row];
        g_cls[row]     = c;
        g_selfsim[row] = sb;
    }
}

// ---------------------------------------------------------------------------
__device__ __forceinline__ void map_tile(int t, int& bi, int& bj) {
    int b = 0, r = t;
    #pragma unroll 1
    while (r >= GI - b) { r -= GI - b; b++; }
    bi = b; bj = b + r;
}

__device__ __forceinline__ void issue_chunk(uint32_t sbase, int ck,
                                            int iBase, int jBase, int tid) {
    #pragma unroll
    for (int q = 0; q < 4; q++) {
        int s  = tid + q * 256;
        int r  = s >> 3;
        int sg = s & 7;
        uint32_t soff = SW128((uint32_t)(r * 128 + sg * 16));
        cp16(sbase + ACH(ck) + soff, g_Pb + (size_t)(iBase + r) * D + ck * 64 + sg * 8);
        cp16(sbase + BCH(ck) + soff, g_Pb + (size_t)(jBase + r) * D + ck * 64 + sg * 8);
    }
    cp_commit();
}

__device__ __forceinline__ void load_frags(uint32_t aB, uint32_t bB, int ks,
                                           int m0, int n0, int lrow, int lkoff,
                                           uint32_t afr[4][4], uint32_t bfr[4][2]) {
    #pragma unroll
    for (int nf2 = 0; nf2 < 2; nf2++) {
        uint32_t r0, r1, r2, r3;
        uint32_t off = (uint32_t)((n0 + nf2 * 16 + lrow) * 128 + lkoff + ks * 32);
        ldsm4(r0, r1, r2, r3, bB + SW128(off));
        bfr[nf2 * 2 + 0][0] = r0; bfr[nf2 * 2 + 0][1] = r2;
        bfr[nf2 * 2 + 1][0] = r1; bfr[nf2 * 2 + 1][1] = r3;
    }
    #pragma unroll
    for (int mf = 0; mf < 4; mf++) {
        uint32_t off = (uint32_t)((m0 + mf * 16 + lrow) * 128 + lkoff + ks * 32);
        ldsm4(afr[mf][0], afr[mf][1], afr[mf][2], afr[mf][3], aB + SW128(off));
    }
}

__device__ __forceinline__ void compute_chunk(uint32_t sbase, int ck,
                                              int m0, int n0, int lrow, int lkoff,
                                              uint32_t afr[2][4][4],
                                              uint32_t bfr[2][4][2],
                                              float acc[4][4][4]) {
    const uint32_t aB = sbase + ACH(ck);
    const uint32_t bB = sbase + BCH(ck);
    load_frags(aB, bB, 0, m0, n0, lrow, lkoff, afr[0], bfr[0]);
    #pragma unroll
    for (int ks = 0; ks < 4; ks++) {
        const int cur = ks & 1;
        if (ks < 3)
            load_frags(aB, bB, ks + 1, m0, n0, lrow, lkoff, afr[cur ^ 1], bfr[cur ^ 1]);
        #pragma unroll
        for (int mf = 0; mf < 4; mf++)
            #pragma unroll
            for (int nf = 0; nf < 4; nf++)
                mma16816(acc[mf][nf], afr[cur][mf], bfr[cur][nf]);
    }
}

// ---------------------------------------------------------------------------
// k_main: persistent CTAs, stride over upper-triangle tiles, cross-tile
// cp.async pipeline (next tile's chunk c issued after step c+1's barrier).
// ---------------------------------------------------------------------------
__global__ void __launch_bounds__(256, 1) k_main() {
    extern __shared__ __align__(128) unsigned char smem[];
    const uint32_t sbase = smem_u32(smem);
    const int tid  = threadIdx.x;
    const int wid  = tid >> 5;
    const int lane = tid & 31;

    int*   clsI  = (int*)(smem + CLSI_OFF);
    int*   clsJ  = (int*)(smem + CLSJ_OFF);
    float* sAccI = (float*)(smem + SACCI_OFF);
    float* sBccI = (float*)(smem + SBCCI_OFF);
    float* sAccJ = (float*)(smem + SACCJ_OFF);
    float* sBccJ = (float*)(smem + SBCCJ_OFF);

    int tile = blockIdx.x;
    if (tile >= NTILES) return;

    int biBlk, bjBlk;
    map_tile(tile, biBlk, bjBlk);
    int iBase = biBlk * TM;
    int jBase = bjBlk * TN;
    bool offdiag = (biBlk != bjBlk);

    // prologue: cls + accum init, issue all 4 chunks of first tile
    if (tid < 128) {
        clsI[tid] = g_cls[iBase + tid];
        sAccI[tid] = 0.0f; sBccI[tid] = 0.0f;
        sAccJ[tid] = 0.0f; sBccJ[tid] = 0.0f;
    } else {
        clsJ[tid - 128] = g_cls[jBase + tid - 128];
    }
    #pragma unroll
    for (int ck = 0; ck < 4; ck++) issue_chunk(sbase, ck, iBase, jBase, tid);

    const int m0 = (wid >> 2) * 64;
    const int n0 = (wid & 3) * 32;
    const int lrow  = lane & 15;
    const int lkoff = (lane >> 4) * 16;
    const int gl   = lane >> 2;
    const int quad = lane & 3;

    #pragma unroll 1
    while (true) {
        int ntile = tile + gridDim.x;
        const bool last = (ntile >= NTILES);
        int nbi, nbj;
        if (last) { nbi = biBlk; nbj = bjBlk; }          // dummy reload
        else      map_tile(ntile, nbi, nbj);
        const int niBase = nbi * TM;
        const int njBase = nbj * TN;

        float acc[4][4][4];
        #pragma unroll
        for (int mf = 0; mf < 4; mf++)
            #pragma unroll
            for (int nf = 0; nf < 4; nf++)
                #pragma unroll
                for (int e = 0; e < 4; e++) acc[mf][nf][e] = 0.0f;

        uint32_t afr[2][4][4], bfr[2][4][2];

        // step 0
        asm volatile("cp.async.wait_group 3;" ::: "memory");
        __syncthreads();
        compute_chunk(sbase, 0, m0, n0, lrow, lkoff, afr, bfr, acc);
        // steps 1..3: wait chunk c, barrier frees buffer c-1, refill it
        asm volatile("cp.async.wait_group 2;" ::: "memory");
        __syncthreads();
        issue_chunk(sbase, 0, niBase, njBase, tid);
        compute_chunk(sbase, 1, m0, n0, lrow, lkoff, afr, bfr, acc);
        asm volatile("cp.async.wait_group 2;" ::: "memory");
        __syncthreads();
        issue_chunk(sbase, 1, niBase, njBase, tid);
        compute_chunk(sbase, 2, m0, n0, lrow, lkoff, afr, bfr, acc);
        asm volatile("cp.async.wait_group 2;" ::: "memory");
        __syncthreads();
        issue_chunk(sbase, 2, niBase, njBase, tid);
        compute_chunk(sbase, 3, m0, n0, lrow, lkoff, afr, bfr, acc);

        // ---- epilogue ----
        int cjr[8];
        #pragma unroll
        for (int q = 0; q < 8; q++)
            cjr[q] = clsJ[n0 + (q >> 1) * 8 + quad * 2 + (q & 1)];

        float aCol[8], bCol[8];
        #pragma unroll
        for (int q = 0; q < 8; q++) { aCol[q] = 0.0f; bCol[q] = 0.0f; }

        #pragma unroll
        for (int rr = 0; rr < 2; rr++) {
            #pragma unroll
            for (int mf = 0; mf < 4; mf++) {
                const int rl = m0 + mf * 16 + gl + rr * 8;
                const int ci = clsI[rl];
                float aRow = 0.0f, bRow = 0.0f;
                #pragma unroll
                for (int q = 0; q < 8; q++) {
                    const float s = acc[mf][q >> 1][rr * 2 + (q & 1)];
                    const bool same = (ci == cjr[q]);
                    const float v = ex2(s * (same ? -EX2SC : EX2SC));
                    const float va = same ? 0.0f : v;
                    const float vb = v - va;
                    aRow += va; bRow += vb;
                    aCol[q] += va; bCol[q] += vb;
                }
                aRow += __shfl_xor_sync(0xffffffffu, aRow, 1);
                aRow += __shfl_xor_sync(0xffffffffu, aRow, 2);
                bRow += __shfl_xor_sync(0xffffffffu, bRow, 1);
                bRow += __shfl_xor_sync(0xffffffffu, bRow, 2);
                if (quad == 0) {
                    atomicAdd(&sAccI[rl], aRow);
                    atomicAdd(&sBccI[rl], bRow);
                }
            }
        }

        if (offdiag) {
            #pragma unroll
            for (int q = 0; q < 8; q++) {
                float a = aCol[q], b = bCol[q];
                #pragma unroll
                for (int o = 4; o <= 16; o <<= 1) {
                    a += __shfl_xor_sync(0xffffffffu, a, o);
                    b += __shfl_xor_sync(0xffffffffu, b, o);
                }
                if (lane < 4) {
                    const int cl = n0 + (q >> 1) * 8 + quad * 2 + (q & 1);
                    atomicAdd(&sAccJ[cl], a);
                    atomicAdd(&sBccJ[cl], b);
                }
            }
        }

        __syncthreads();                      // epilogue done; buffer 3 free
        issue_chunk(sbase, 3, niBase, njBase, tid);

        // flush to global, reset accumulators, load next tile's classes
        if (tid < 128) {
            atomicAdd(&g_A[iBase + tid], sAccI[tid]);
            atomicAdd(&g_B[iBase + tid], sBccI[tid]);
            if (offdiag) {
                atomicAdd(&g_A[jBase + tid], sAccJ[tid]);
                atomicAdd(&g_B[jBase + tid], sBccJ[tid]);
            }
            sAccI[tid] = 0.0f; sBccI[tid] = 0.0f;
            sAccJ[tid] = 0.0f; sBccJ[tid] = 0.0f;
            clsI[tid] = g_cls[niBase + tid];
        } else {
            clsJ[tid - 128] = g_cls[njBase + tid - 128];
        }

        if (last) break;
        tile = ntile; biBlk = nbi; bjBlk = nbj;
        iBase = niBase; jBase = njBase;
        offdiag = (nbi != nbj);
    }
}

// ---------------------------------------------------------------------------
// k_loss: histogram locally, subtract self term, empty-set semantics, mean
// ---------------------------------------------------------------------------
__global__ void k_loss(float* __restrict__ out) {
    __shared__ float red[256];
    __shared__ int hist[16];
    const int tid = threadIdx.x;
    if (tid < 16) hist[tid] = 0;
    __syncthreads();
    for (int r = tid; r < N; r += 256) atomicAdd(&hist[g_cls[r] & 15], 1);
    __syncthreads();

    const float MF = __expf(0.5f * INV_T);
    float sum = 0.0f;
    for (int r = tid; r < N; r += 256) {
        int   c   = g_cls[r] & 15;
        int   cnt = hist[c];
        float Bv  = g_B[r] - __expf(-g_selfsim[r] * INV_T);
        float Av  = (N - cnt > 0) ? g_A[r] : 1.0f;
        Bv        = (cnt - 1 > 0) ? Bv : 1.0f;
        sum += log1pf(MF * Av * Bv);
    }
    red[tid] = sum;
    __syncthreads();
    #pragma unroll
    for (int s = 128; s; s >>= 1) {
        if (tid < s) red[tid] += red[tid + s];
        __syncthreads();
    }
    if (tid == 0) out[0] = red[0] / (float)N;
}

// ---------------------------------------------------------------------------
extern "C" void kernel_launch(void* const* d_in, const int* in_sizes, int n_in,
                              void* d_out, int out_size) {
    const float* P = (const float*)d_in[0];
    const void*  y = d_in[1];
    float*     out = (float*)d_out;

    cudaFuncSetAttribute(k_main, cudaFuncAttributeMaxDynamicSharedMemorySize,
                         SMEM_BYTES);

    int sms = 148;
    cudaDeviceGetAttribute(&sms, cudaDevAttrMultiProcessorCount, 0);
    int grid = sms < NTILES ? sms : NTILES;

    k_norm<<<N / 8, 256>>>(P, y);
    k_main<<<grid, 256, SMEM_BYTES>>>();
    k_loss<<<1, 256>>>(out);
}